// round 2
// baseline (speedup 1.0000x reference)
#include <cuda_runtime.h>
#include <math.h>

#define NPTS 32768
#define NB 16
#define WSTRIDE 4560   // per-batch hyper weights: 30*62 + 3*30*30

// ---------------- scratch (device globals; no allocations allowed) ----------
__device__ float g_W[NB * WSTRIDE];          // normalized hyper weights
__device__ float g_enc[NPTS * 64];           // nerf encoding, padded to 64
__device__ float g_g[NB * NPTS * 30];        // output of hyper layers (63MB)

// ---------------- helpers ---------------------------------------------------
__device__ __forceinline__ float silu_f(float z) {
    // z * sigmoid(z); robust at extremes (exp->inf => 0, exp->0 => z)
    float e = __expf(-z);
    return __fdividef(z, 1.0f + e);
}

// Accurate sin for |x| up to ~1e5 regardless of -use_fast_math:
// double Cody-Waite reduction + fp32 minimax polynomial.
__device__ __forceinline__ float sin_accurate(float xf) {
    double x = (double)xf;
    double kd = rint(x * 0.63661977236758138);      // x * 2/pi
    long long ki = (long long)kd;
    double r = fma(kd, -1.5707963267948966, x);     // pi/2 hi
    r = fma(kd, -6.123233995736766e-17, r);         // pi/2 lo
    float rf = (float)r;
    float s2 = rf * rf;
    // sin poly on [-pi/4, pi/4]
    float ps = fmaf(s2, 2.7525562e-6f, -1.9840874e-4f);
    ps = fmaf(s2, ps, 8.3333310e-3f);
    ps = fmaf(s2, ps, -1.6666667e-1f);
    float sinv = fmaf(rf * s2, ps, rf);
    // cos poly
    float pc = fmaf(s2, 2.4433157e-5f, -1.3888378e-3f);
    pc = fmaf(s2, pc, 4.1666638e-2f);
    pc = fmaf(s2, pc, -0.5f);
    float cosv = fmaf(s2, pc, 1.0f);
    int q = (int)(ki & 3);
    float res = (q & 1) ? cosv : sinv;
    if (q & 2) res = -res;
    return res;
}

// ---------------- K0: nerf encoding -----------------------------------------
__global__ __launch_bounds__(256) void enc_kernel(const float* __restrict__ x) {
    int p = blockIdx.x * 256 + threadIdx.x;
    float x0 = x[2 * p], x1 = x[2 * p + 1];
    float* o = g_enc + p * 64;
    const float HPI = 1.5707963267948966f;  // f32(pi/2), matches reference's f32 add
    o[0] = x0; o[1] = x1;
#pragma unroll
    for (int s = 0; s < 15; ++s) {
        float sc = (float)(1 << s);
        float a0 = x0 * sc, a1 = x1 * sc;
        o[2 + 2 * s]  = sin_accurate(a0);
        o[3 + 2 * s]  = sin_accurate(a1);
        o[32 + 2 * s] = sin_accurate(a0 + HPI);
        o[33 + 2 * s] = sin_accurate(a1 + HPI);
    }
    o[62] = 0.0f; o[63] = 0.0f;
}

// ---------------- K1: hyper weight generation + layernorm -------------------
__global__ __launch_bounds__(128) void hyperw_kernel(
    const float* __restrict__ sdf, const float* __restrict__ pw,
    const float* __restrict__ pb, const float* __restrict__ lnw,
    const float* __restrict__ lnb, int li, int c, int woff) {
    __shared__ float wbuf[30 * 62];
    int b = blockIdx.x;
    int tid = threadIdx.x;
    int tot = 30 * c;
    for (int e = tid; e < tot; e += 128) {
        int v = e / c, cc = e - v * c;
        const float4* sl4 = (const float4*)(sdf + ((b * 120) + li * 30 + v) * 120);
        const float4* pw4 = (const float4*)(pw + (v * c + cc) * 120);
        float acc = 0.0f;
#pragma unroll
        for (int d = 0; d < 30; ++d) {
            float4 a = sl4[d], w = pw4[d];
            acc = fmaf(a.x, w.x, acc); acc = fmaf(a.y, w.y, acc);
            acc = fmaf(a.z, w.z, acc); acc = fmaf(a.w, w.w, acc);
        }
        wbuf[e] = acc + pb[e];
    }
    __syncthreads();
    for (int v = tid; v < 30; v += 128) {
        const float* row = wbuf + v * c;
        float mu = 0.0f;
        for (int cc = 0; cc < c; ++cc) mu += row[cc];
        mu /= (float)c;
        float var = 0.0f;
        for (int cc = 0; cc < c; ++cc) { float d = row[cc] - mu; var = fmaf(d, d, var); }
        var /= (float)c;
        float inv = rsqrtf(var + 1e-5f);
        float* dst = g_W + b * WSTRIDE + woff + v * c;
        for (int cc = 0; cc < c; ++cc)
            dst[cc] = (row[cc] - mu) * inv * lnw[cc] + lnb[cc];
    }
}

// ---------------- K2: apply 4 hyper layers ----------------------------------
__global__ __launch_bounds__(256) void hyper_apply_kernel(
    const float* __restrict__ b0, const float* __restrict__ b1,
    const float* __restrict__ b2, const float* __restrict__ b3) {
    __shared__ float sW[WSTRIDE];
    __shared__ float sb[120];
    int b = blockIdx.y;
    int tid = threadIdx.x;
    const float* Wb = g_W + b * WSTRIDE;
    for (int i = tid; i < WSTRIDE; i += 256) sW[i] = Wb[i];
    if (tid < 30) sb[tid] = b0[tid];
    else if (tid < 60) sb[tid] = b1[tid - 30];
    else if (tid < 90) sb[tid] = b2[tid - 60];
    else if (tid < 120) sb[tid] = b3[tid - 90];
    __syncthreads();

    int p = blockIdx.x * 256 + tid;
    float h[62];
    const float4* e4 = (const float4*)(g_enc + p * 64);
#pragma unroll
    for (int i = 0; i < 15; ++i) {
        float4 v = e4[i];
        h[4 * i] = v.x; h[4 * i + 1] = v.y; h[4 * i + 2] = v.z; h[4 * i + 3] = v.w;
    }
    { float4 v = e4[15]; h[60] = v.x; h[61] = v.y; }

    float a[30];
    // layer 0: 62 -> 30
#pragma unroll
    for (int oo = 0; oo < 30; ++oo) {
        const float2* w = (const float2*)(sW + oo * 62);
        float acc = 0.0f;
#pragma unroll
        for (int i = 0; i < 31; ++i) {
            float2 ww = w[i];
            acc = fmaf(h[2 * i], ww.x, acc);
            acc = fmaf(h[2 * i + 1], ww.y, acc);
        }
        a[oo] = silu_f(acc + sb[oo]);
    }
    // layers 1..3: 30 -> 30
#pragma unroll
    for (int l = 1; l <= 3; ++l) {
        int off = 1860 + (l - 1) * 900;
        float t[30];
#pragma unroll
        for (int oo = 0; oo < 30; ++oo) {
            const float2* w = (const float2*)(sW + off + oo * 30);
            float acc = 0.0f;
#pragma unroll
            for (int i = 0; i < 15; ++i) {
                float2 ww = w[i];
                acc = fmaf(a[2 * i], ww.x, acc);
                acc = fmaf(a[2 * i + 1], ww.y, acc);
            }
            t[oo] = silu_f(acc + sb[l * 30 + oo]);
        }
#pragma unroll
        for (int oo = 0; oo < 30; ++oo) a[oo] = t[oo];
    }
    float* gout = g_g + (b * NPTS + p) * 30;
#pragma unroll
    for (int i = 0; i < 15; ++i)
        ((float2*)gout)[i] = make_float2(a[2 * i], a[2 * i + 1]);
}

// ---------------- K3: fused MLP 30->256->128->1 -----------------------------
// 4 lanes cooperate per point: lane q owns h1[q*64 .. q*64+63] and h2[{4*j8+q}].
#define K3_SW0_SZ (256 * 32 + 16)
#define K3_SW1_PITCH 260
#define K3_SMEM_FLOATS (K3_SW0_SZ + 256 + 128 * K3_SW1_PITCH + 128 + 128)
#define K3_SMEM_BYTES (K3_SMEM_FLOATS * 4)

__global__ __launch_bounds__(256, 1) void mlp_kernel(
    const float* __restrict__ w0, const float* __restrict__ b0,
    const float* __restrict__ w1, const float* __restrict__ b1,
    const float* __restrict__ w2, const float* __restrict__ b2v,
    float* __restrict__ out) {
    extern __shared__ float sm[];
    float* sW0 = sm;                       // swizzled rows: k*32 + (k>>6)*4
    float* sB0 = sW0 + K3_SW0_SZ;
    float* sW1 = sB0 + 256;                // pitch 260 -> conflict-free float4
    float* sB1 = sW1 + 128 * K3_SW1_PITCH;
    float* sW2 = sB1 + 128;

    int tid = threadIdx.x;
    {
        int k = tid;  // 256 threads, 256 rows
#pragma unroll
        for (int i = 0; i < 30; ++i)
            sW0[k * 32 + (k >> 6) * 4 + i] = w0[k * 30 + i];
        sW0[k * 32 + (k >> 6) * 4 + 30] = 0.0f;
        sW0[k * 32 + (k >> 6) * 4 + 31] = 0.0f;
        sB0[tid] = b0[tid];
        if (tid < 128) { sB1[tid] = b1[tid]; sW2[tid] = w2[tid]; }
    }
    for (int idx = tid; idx < 128 * 256; idx += 256) {
        int j = idx >> 8, k = idx & 255;
        sW1[j * K3_SW1_PITCH + k] = w1[idx];
    }
    float bias2 = __ldg(b2v);
    __syncthreads();

    int lane = tid & 31, warp = tid >> 5;
    int q = lane & 3, pp = lane >> 2;
    int grp = warp * 8 + pp;             // 0..63 point groups per block
    int b = blockIdx.y;

#pragma unroll 1
    for (int it = 0; it < 4; ++it) {
        int p = blockIdx.x * 256 + it * 64 + grp;
        const float2* g2 = (const float2*)(g_g + (b * NPTS + p) * 30);
        float gv[30];
#pragma unroll
        for (int i = 0; i < 15; ++i) { float2 v = g2[i]; gv[2 * i] = v.x; gv[2 * i + 1] = v.y; }

        // phase 1: h1 chunk (64 values), silu
        float s[64];
        const float* w0row0 = sW0 + q * 64 * 32 + q * 4;
#pragma unroll
        for (int m = 0; m < 64; ++m) {
            const float4* wr = (const float4*)(w0row0 + m * 32);
            float acc = sB0[q * 64 + m];
#pragma unroll
            for (int i4 = 0; i4 < 7; ++i4) {
                float4 w = wr[i4];
                acc = fmaf(gv[4 * i4], w.x, acc);
                acc = fmaf(gv[4 * i4 + 1], w.y, acc);
                acc = fmaf(gv[4 * i4 + 2], w.z, acc);
                acc = fmaf(gv[4 * i4 + 3], w.w, acc);
            }
            {
                float2 wt = *(const float2*)((const float*)wr + 28);
                acc = fmaf(gv[28], wt.x, acc);
                acc = fmaf(gv[29], wt.y, acc);
            }
            s[m] = silu_f(acc);
        }

        // phase 2: h2 accumulation over all 256 h1 values (shfl exchange)
        float acc2[32];
#pragma unroll
        for (int j8 = 0; j8 < 32; ++j8) acc2[j8] = sB1[4 * j8 + q];

#pragma unroll 1
        for (int qs = 0; qs < 4; ++qs) {
            int srcl = (pp << 2) | qs;
#pragma unroll
            for (int m4 = 0; m4 < 16; ++m4) {
                float sk0 = __shfl_sync(0xffffffffu, s[4 * m4 + 0], srcl);
                float sk1 = __shfl_sync(0xffffffffu, s[4 * m4 + 1], srcl);
                float sk2 = __shfl_sync(0xffffffffu, s[4 * m4 + 2], srcl);
                float sk3 = __shfl_sync(0xffffffffu, s[4 * m4 + 3], srcl);
                const float* wbase = sW1 + q * K3_SW1_PITCH + (qs * 64 + 4 * m4);
#pragma unroll
                for (int j8 = 0; j8 < 32; ++j8) {
                    float4 w = *(const float4*)(wbase + j8 * 4 * K3_SW1_PITCH);
                    acc2[j8] = fmaf(sk0, w.x,
                                fmaf(sk1, w.y,
                                 fmaf(sk2, w.z,
                                  fmaf(sk3, w.w, acc2[j8]))));
                }
            }
        }

        // epilogue: out = sum_j w2[j]*silu(h2[j]) + b2, reduced over the 4 lanes
        float r = 0.0f;
#pragma unroll
        for (int j8 = 0; j8 < 32; ++j8)
            r = fmaf(sW2[4 * j8 + q], silu_f(acc2[j8]), r);
        r += __shfl_xor_sync(0xffffffffu, r, 1);
        r += __shfl_xor_sync(0xffffffffu, r, 2);
        if (q == 0) out[b * NPTS + p] = r + bias2;
    }
}

// ---------------- launch -----------------------------------------------------
extern "C" void kernel_launch(void* const* d_in, const int* in_sizes, int n_in,
                              void* d_out, int out_size) {
    const float* x   = (const float*)d_in[0];
    const float* sdf = (const float*)d_in[1];
    const float* pw[4]   = {(const float*)d_in[2],  (const float*)d_in[7],
                            (const float*)d_in[12], (const float*)d_in[17]};
    const float* pb[4]   = {(const float*)d_in[3],  (const float*)d_in[8],
                            (const float*)d_in[13], (const float*)d_in[18]};
    const float* lnw[4]  = {(const float*)d_in[4],  (const float*)d_in[9],
                            (const float*)d_in[14], (const float*)d_in[19]};
    const float* lnb[4]  = {(const float*)d_in[5],  (const float*)d_in[10],
                            (const float*)d_in[15], (const float*)d_in[20]};
    const float* bias[4] = {(const float*)d_in[6],  (const float*)d_in[11],
                            (const float*)d_in[16], (const float*)d_in[21]};
    const float* mw0 = (const float*)d_in[22];
    const float* mb0 = (const float*)d_in[23];
    const float* mw1 = (const float*)d_in[24];
    const float* mb1 = (const float*)d_in[25];
    const float* mw2 = (const float*)d_in[26];
    const float* mb2 = (const float*)d_in[27];
    float* out = (float*)d_out;

    cudaFuncSetAttribute(mlp_kernel, cudaFuncAttributeMaxDynamicSharedMemorySize,
                         K3_SMEM_BYTES);

    enc_kernel<<<NPTS / 256, 256>>>(x);

    const int cs[4]    = {62, 30, 30, 30};
    const int woffs[4] = {0, 1860, 2760, 3660};
    for (int li = 0; li < 4; ++li)
        hyperw_kernel<<<NB, 128>>>(sdf, pw[li], pb[li], lnw[li], lnb[li],
                                   li, cs[li], woffs[li]);

    dim3 g2(NPTS / 256, NB);
    hyper_apply_kernel<<<g2, 256>>>(bias[0], bias[1], bias[2], bias[3]);

    dim3 g3(NPTS / 256, NB);
    mlp_kernel<<<g3, 256, K3_SMEM_BYTES>>>(mw0, mb0, mw1, mb1, mw2, mb2, out);
}